// round 2
// baseline (speedup 1.0000x reference)
#include <cuda_runtime.h>

// FusionMarkovGNN — algebraically collapsed implementation.
//
// mss[n] has, per (k,b) column-slice, one of 3 states determined by the sign
// pattern of adj rows k*16..k*16+15 at column b:
//   relu-state (any>0, not all): mss[k,:,b] = max(adj[:,b],0)
//   full-state (all>0):          mss[k,:,b] = adj[:,b]
//   zero-state (none>0):         mss[k,:,b] = 0
// So W_eff[n,l] = conv_w[l] @ mss[n] (256x256) =
//   wsum_l @ relu(adj_n)                       (k-independent bulk term)
//   + rare exact corrections for full/zero states.
// Then per layer: y = relu(BN(W_eff[n,l] @ x + conv_b)).

#define CC 256
#define SS 16
#define HW 1024
#define NB 4

__device__ float g_wsum[3 * CC * CC];           // [l][o][a]
__device__ float g_weff[NB * 3 * CC * CC];      // [n][l][o][b]
__device__ unsigned char g_flags[NB * SS * CC]; // 0=relu, 1=full, 2=zero

// ---------------------------------------------------------------- flags
__global__ void flags_kernel(const float* __restrict__ adj) {
    int n = blockIdx.x, k = blockIdx.y, b = threadIdx.x;
    const float* m = adj + n * CC * CC;
    bool anyp = false, allp = true;
#pragma unroll
    for (int i = 0; i < 16; i++) {
        float v = m[(k * 16 + i) * CC + b];
        anyp = anyp || (v > 0.0f);
        allp = allp && (v > 0.0f);
    }
    g_flags[(n * SS + k) * CC + b] = allp ? 1 : (anyp ? 0 : 2);
}

// ---------------------------------------------------------------- wsum
// wsum[l][o][a] = sum_k conv_w[l][o][k*256 + a]
__global__ void wsum_kernel(const float* __restrict__ w) {
    int idx = blockIdx.x * 256 + threadIdx.x;   // 3*65536 threads
    int l  = idx >> 16;
    int oa = idx & 0xFFFF;
    int o = oa >> 8, a = oa & 255;
    const float* base = w + (size_t)l * CC * SS * CC + (size_t)o * (SS * CC) + a;
    float s = 0.0f;
#pragma unroll
    for (int k = 0; k < 16; k++) s += base[k * CC];
    g_wsum[idx] = s;
}

// ---------------------------------------------------------------- W_eff GEMM
// g_weff[n][l] = wsum[l] @ relu(adj[n]) ; M=N=K=256
__global__ __launch_bounds__(256) void weff_kernel(const float* __restrict__ adj) {
    int nl = blockIdx.z;                 // n*3 + l
    const float* A = g_wsum + (size_t)(nl % 3) * (CC * CC);   // [o][a]
    const float* B = adj    + (size_t)(nl / 3) * (CC * CC);   // [a][b]
    float* Cc = g_weff + (size_t)nl * (CC * CC);

    __shared__ float As[16][64];
    __shared__ float Bs[16][64];

    int tid = threadIdx.x;
    int row0 = blockIdx.y * 64;   // o
    int col0 = blockIdx.x * 64;   // b
    int tr = tid >> 4, tc = tid & 15;
    int arow = tid >> 2, acol4 = (tid & 3) * 4;
    int brow = tid >> 4, bcol4 = (tid & 15) * 4;

    float acc[4][4] = {};

    for (int k0 = 0; k0 < CC; k0 += 16) {
        float4 av = *(const float4*)(A + (row0 + arow) * CC + k0 + acol4);
        As[acol4 + 0][arow] = av.x;
        As[acol4 + 1][arow] = av.y;
        As[acol4 + 2][arow] = av.z;
        As[acol4 + 3][arow] = av.w;
        float4 bv = *(const float4*)(B + (k0 + brow) * CC + col0 + bcol4);
        bv.x = fmaxf(bv.x, 0.0f); bv.y = fmaxf(bv.y, 0.0f);
        bv.z = fmaxf(bv.z, 0.0f); bv.w = fmaxf(bv.w, 0.0f);
        *(float4*)&Bs[brow][bcol4] = bv;
        __syncthreads();
#pragma unroll
        for (int k = 0; k < 16; k++) {
            float4 a4 = *(const float4*)&As[k][tr * 4];
            float4 b4 = *(const float4*)&Bs[k][tc * 4];
            float af[4] = {a4.x, a4.y, a4.z, a4.w};
            float bf[4] = {b4.x, b4.y, b4.z, b4.w};
#pragma unroll
            for (int i = 0; i < 4; i++)
#pragma unroll
                for (int j = 0; j < 4; j++)
                    acc[i][j] = fmaf(af[i], bf[j], acc[i][j]);
        }
        __syncthreads();
    }

#pragma unroll
    for (int i = 0; i < 4; i++) {
        int o = row0 + tr * 4 + i;
        float4 v;
        v.x = acc[i][0]; v.y = acc[i][1]; v.z = acc[i][2]; v.w = acc[i][3];
        *(float4*)(Cc + o * CC + col0 + tc * 4) = v;
    }
}

// ---------------------------------------------------------------- corrections
// For each (n,k,b) with flag != relu, fix W_eff exactly:
//  flag=1 (full): += sum_a w[l][o][k*256+a] * min(m[a][b], 0)
//  flag=2 (zero): -= sum_a w[l][o][k*256+a] * max(m[a][b], 0)
// atomicAdd: k-blocks of the same (n,l) may touch the same (o,b).
__global__ __launch_bounds__(256) void corr_kernel(const float* __restrict__ adj,
                                                   const float* __restrict__ w) {
    int k = blockIdx.x, l = blockIdx.y, n = blockIdx.z;
    int o = threadIdx.x;

    __shared__ unsigned char fl[CC];
    __shared__ float mcol[CC];

    fl[o] = g_flags[(n * SS + k) * CC + o];
    __syncthreads();

    const float* wrow = w + (size_t)l * CC * SS * CC + (size_t)o * (SS * CC) + k * CC;
    const float* m = adj + (size_t)n * CC * CC;
    float* Wd = g_weff + (size_t)(n * 3 + l) * (CC * CC);

    for (int b = 0; b < CC; b++) {
        unsigned char f = fl[b];        // uniform across the block
        if (f == 0) continue;
        __syncthreads();
        mcol[o] = m[o * CC + b];        // reuse o as the 'a' index
        __syncthreads();
        float ssum = 0.0f;
        if (f == 1) {
            for (int a = 0; a < CC; a++) ssum = fmaf(wrow[a], fminf(mcol[a], 0.0f), ssum);
        } else {
            for (int a = 0; a < CC; a++) ssum = fmaf(-wrow[a], fmaxf(mcol[a], 0.0f), ssum);
        }
        atomicAdd(&Wd[o * CC + b], ssum);
    }
}

// ---------------------------------------------------------------- layer GEMM + BN + ReLU
// y[n][o][p] = relu( (sum_b Weff[n][l][o][b]*x[n][b][p] + cb[o] - mean[o])*scale[o] + beta[o] )
__global__ __launch_bounds__(256) void layer_kernel(
    const float* __restrict__ x,       // [4][256][1024]
    float* __restrict__ y,             // [4][256][1024]
    int l,
    const float* __restrict__ cb,
    const float* __restrict__ gamma,
    const float* __restrict__ beta,
    const float* __restrict__ mean,
    const float* __restrict__ var) {
    int n = blockIdx.z;
    const float* A = g_weff + (size_t)(n * 3 + l) * (CC * CC);  // [o][b]
    const float* B = x + (size_t)n * (CC * HW);                 // [b][p]
    float* Cc = y + (size_t)n * (CC * HW);

    __shared__ float As[16][64];
    __shared__ float Bs[16][64];

    int tid = threadIdx.x;
    int row0 = blockIdx.y * 64;   // o
    int col0 = blockIdx.x * 64;   // p
    int tr = tid >> 4, tc = tid & 15;
    int arow = tid >> 2, acol4 = (tid & 3) * 4;
    int brow = tid >> 4, bcol4 = (tid & 15) * 4;

    float acc[4][4] = {};

    for (int k0 = 0; k0 < CC; k0 += 16) {
        float4 av = *(const float4*)(A + (row0 + arow) * CC + k0 + acol4);
        As[acol4 + 0][arow] = av.x;
        As[acol4 + 1][arow] = av.y;
        As[acol4 + 2][arow] = av.z;
        As[acol4 + 3][arow] = av.w;
        float4 bv = *(const float4*)(B + (k0 + brow) * HW + col0 + bcol4);
        *(float4*)&Bs[brow][bcol4] = bv;
        __syncthreads();
#pragma unroll
        for (int k = 0; k < 16; k++) {
            float4 a4 = *(const float4*)&As[k][tr * 4];
            float4 b4 = *(const float4*)&Bs[k][tc * 4];
            float af[4] = {a4.x, a4.y, a4.z, a4.w};
            float bf[4] = {b4.x, b4.y, b4.z, b4.w};
#pragma unroll
            for (int i = 0; i < 4; i++)
#pragma unroll
                for (int j = 0; j < 4; j++)
                    acc[i][j] = fmaf(af[i], bf[j], acc[i][j]);
        }
        __syncthreads();
    }

#pragma unroll
    for (int i = 0; i < 4; i++) {
        int o = row0 + tr * 4 + i;
        float sc  = gamma[o] * rsqrtf(var[o] + 1e-5f);
        float add = (cb[o] - mean[o]) * sc + beta[o];
        float4 v;
        v.x = fmaxf(fmaf(acc[i][0], sc, add), 0.0f);
        v.y = fmaxf(fmaf(acc[i][1], sc, add), 0.0f);
        v.z = fmaxf(fmaf(acc[i][2], sc, add), 0.0f);
        v.w = fmaxf(fmaf(acc[i][3], sc, add), 0.0f);
        *(float4*)(Cc + o * HW + col0 + tc * 4) = v;
    }
}

// ---------------------------------------------------------------- launch
extern "C" void kernel_launch(void* const* d_in, const int* in_sizes, int n_in,
                              void* d_out, int out_size) {
    (void)in_sizes; (void)n_in; (void)out_size;
    const float* feats = (const float*)d_in[0];  // [4,256,32,32]
    const float* adj   = (const float*)d_in[1];  // [4,256,256]
    const float* convw = (const float*)d_in[2];  // [3,256,4096]
    const float* convb = (const float*)d_in[3];  // [3,256]
    const float* gamma = (const float*)d_in[4];
    const float* beta  = (const float*)d_in[5];
    const float* mean  = (const float*)d_in[6];
    const float* var   = (const float*)d_in[7];
    float* out = (float*)d_out;                  // [3,4,256,32,32]

    flags_kernel<<<dim3(NB, SS), 256>>>(adj);
    wsum_kernel<<<768, 256>>>(convw);
    weff_kernel<<<dim3(4, 4, NB * 3), 256>>>(adj);
    corr_kernel<<<dim3(SS, 3, NB), 256>>>(adj, convw);

    const size_t SEC = (size_t)NB * CC * HW;     // floats per layer output
    for (int l = 0; l < 3; l++) {
        const float* x = (l == 0) ? feats : (out + (size_t)(l - 1) * SEC);
        layer_kernel<<<dim3(16, 4, NB), 256>>>(
            x, out + (size_t)l * SEC, l,
            convb + l * CC, gamma + l * CC, beta + l * CC,
            mean + l * CC, var + l * CC);
    }
}

// round 3
// speedup vs baseline: 1.0783x; 1.0783x over previous
#include <cuda_runtime.h>

// FusionMarkovGNN — algebraically collapsed.
//   W_eff[n,l] = conv_w[l] @ mss[n] = wsum_l @ relu(adj_n) + rare exact
//   corrections (full/zero sign-pattern columns, gathered into a list).
//   Per layer: y = relu(BN(W_eff[n,l] @ x + conv_b)).
// GEMMs use packed fp32 FFMA2 via PTX fma.rn.f32x2.

#define CC 256
#define SS 16
#define HW 1024
#define NB 4

typedef unsigned long long u64;

__device__ float g_wsum[3 * CC * CC];       // [l][o][a]
__device__ float g_weff[NB * 3 * CC * CC];  // [n][l][o][b]
__device__ int   g_ncorr;
__device__ int   g_corr[NB * SS * CC];      // capacity == one per (n,k,b)

// ---------------------------------------------------------------- f32x2 helpers
__device__ __forceinline__ void ffma2(u64& d, u64 a, u64 b) {
    asm("fma.rn.f32x2 %0, %1, %2, %0;" : "+l"(d) : "l"(a), "l"(b));
}
__device__ __forceinline__ u64 dupf(float x) {
    u64 r; asm("mov.b64 %0, {%1, %1};" : "=l"(r) : "f"(x)); return r;
}
__device__ __forceinline__ float2 unpk(u64 v) {
    float2 r; asm("mov.b64 {%0, %1}, %2;" : "=f"(r.x), "=f"(r.y) : "l"(v)); return r;
}

// ---------------------------------------------------------------- reset
__global__ void reset_kernel() { g_ncorr = 0; }

// ---------------------------------------------------------------- detect exceptions
// state 1 = full (all 16 rows > 0), state 2 = zero (none > 0)
__global__ void detect_kernel(const float* __restrict__ adj) {
    int n = blockIdx.x, k = blockIdx.y, b = threadIdx.x;
    const float* m = adj + n * CC * CC;
    bool anyp = false, allp = true;
#pragma unroll
    for (int i = 0; i < 16; i++) {
        float v = m[(k * 16 + i) * CC + b];
        anyp = anyp || (v > 0.0f);
        allp = allp && (v > 0.0f);
    }
    if (allp || !anyp) {
        int idx = atomicAdd(&g_ncorr, 1);
        g_corr[idx] = (n << 16) | (k << 10) | (b << 2) | (allp ? 1 : 2);
    }
}

// ---------------------------------------------------------------- wsum
// wsum[l][o][a] = sum_k conv_w[l][o][k*256 + a]
__global__ void wsum_kernel(const float* __restrict__ w) {
    int idx = blockIdx.x * 256 + threadIdx.x;   // 3*65536 threads
    int l  = idx >> 16;
    int oa = idx & 0xFFFF;
    int o = oa >> 8, a = oa & 255;
    const float* base = w + (size_t)l * CC * SS * CC + (size_t)o * (SS * CC) + a;
    float s = 0.0f;
#pragma unroll
    for (int k = 0; k < 16; k++) s += base[k * CC];
    g_wsum[idx] = s;
}

// ---------------------------------------------------------------- W_eff GEMM
// g_weff[n][l] = wsum[l] @ relu(adj[n]); M=N=K=256. 64x128 tile, f32x2.
__global__ __launch_bounds__(256) void weff_kernel(const float* __restrict__ adj) {
    int nl = blockIdx.z;                 // n*3 + l
    const float* A = g_wsum + (size_t)(nl % 3) * (CC * CC);   // [o][a]
    const float* B = adj    + (size_t)(nl / 3) * (CC * CC);   // [a][b]
    float* Cc = g_weff + (size_t)nl * (CC * CC);

    __shared__ float As[16][64];
    __shared__ float Bs[16][128];

    int tid = threadIdx.x;
    int row0 = blockIdx.y * 64;    // o
    int col0 = blockIdx.x * 128;   // b
    int tr = tid >> 4, tc = tid & 15;
    int arow = tid >> 2, acol4 = (tid & 3) * 4;
    int brow = tid >> 4, bcol = (tid & 15) * 8;

    u64 acc[4][4] = {};   // [row][pair]: pairs 0,1 -> cols tc*4..; 2,3 -> 64+tc*4..

    for (int k0 = 0; k0 < CC; k0 += 16) {
        float4 av = *(const float4*)(A + (row0 + arow) * CC + k0 + acol4);
        As[acol4 + 0][arow] = av.x;
        As[acol4 + 1][arow] = av.y;
        As[acol4 + 2][arow] = av.z;
        As[acol4 + 3][arow] = av.w;
        float4 b0 = *(const float4*)(B + (k0 + brow) * CC + col0 + bcol);
        float4 b1 = *(const float4*)(B + (k0 + brow) * CC + col0 + bcol + 4);
        b0.x = fmaxf(b0.x, 0.0f); b0.y = fmaxf(b0.y, 0.0f);
        b0.z = fmaxf(b0.z, 0.0f); b0.w = fmaxf(b0.w, 0.0f);
        b1.x = fmaxf(b1.x, 0.0f); b1.y = fmaxf(b1.y, 0.0f);
        b1.z = fmaxf(b1.z, 0.0f); b1.w = fmaxf(b1.w, 0.0f);
        *(float4*)&Bs[brow][bcol]     = b0;
        *(float4*)&Bs[brow][bcol + 4] = b1;
        __syncthreads();
#pragma unroll
        for (int k = 0; k < 16; k++) {
            float4 a4 = *(const float4*)&As[k][tr * 4];
            ulonglong2 blo = *(const ulonglong2*)&Bs[k][tc * 4];
            ulonglong2 bhi = *(const ulonglong2*)&Bs[k][64 + tc * 4];
            u64 ad[4] = {dupf(a4.x), dupf(a4.y), dupf(a4.z), dupf(a4.w)};
#pragma unroll
            for (int i = 0; i < 4; i++) {
                ffma2(acc[i][0], ad[i], blo.x);
                ffma2(acc[i][1], ad[i], blo.y);
                ffma2(acc[i][2], ad[i], bhi.x);
                ffma2(acc[i][3], ad[i], bhi.y);
            }
        }
        __syncthreads();
    }

#pragma unroll
    for (int i = 0; i < 4; i++) {
        int o = row0 + tr * 4 + i;
        float2 p0 = unpk(acc[i][0]), p1 = unpk(acc[i][1]);
        float2 p2 = unpk(acc[i][2]), p3 = unpk(acc[i][3]);
        float4 v0 = {p0.x, p0.y, p1.x, p1.y};
        float4 v1 = {p2.x, p2.y, p3.x, p3.y};
        *(float4*)(Cc + o * CC + col0 + tc * 4)      = v0;
        *(float4*)(Cc + o * CC + col0 + 64 + tc * 4) = v1;
    }
}

// ---------------------------------------------------------------- corrections
// For each listed (n,k,b):
//  full: += sum_a w[l][o][k*256+a] * min(m[a][b], 0)
//  zero: -= sum_a w[l][o][k*256+a] * max(m[a][b], 0)
__global__ __launch_bounds__(256) void corr2_kernel(const float* __restrict__ adj,
                                                    const float* __restrict__ w) {
    int l = blockIdx.x;
    int o = threadIdx.x;
    __shared__ float mcol[CC];
    int ncorr = g_ncorr;
    for (int e = 0; e < ncorr; e++) {
        int ent = g_corr[e];
        int n = ent >> 16, k = (ent >> 10) & 0x3F, b = (ent >> 2) & 0xFF, st = ent & 3;
        __syncthreads();
        mcol[o] = adj[(size_t)n * CC * CC + o * CC + b];   // o reused as 'a'
        __syncthreads();
        const float* wrow = w + (size_t)l * CC * SS * CC + (size_t)o * (SS * CC) + k * CC;
        float s = 0.0f;
        if (st == 1) {
            for (int a = 0; a < CC; a++) s = fmaf(wrow[a], fminf(mcol[a], 0.0f), s);
        } else {
            for (int a = 0; a < CC; a++) s = fmaf(-wrow[a], fmaxf(mcol[a], 0.0f), s);
        }
        atomicAdd(&g_weff[(size_t)(n * 3 + l) * CC * CC + o * CC + b], s);
    }
}

// ---------------------------------------------------------------- layer GEMM + BN + ReLU
// 64x128 tile, f32x2 FMA. Grid (8, 4, 4) = 128 blocks (one wave).
__global__ __launch_bounds__(256) void layer_kernel(
    const float* __restrict__ x,       // [4][256][1024]
    float* __restrict__ y,             // [4][256][1024]
    int l,
    const float* __restrict__ cb,
    const float* __restrict__ gamma,
    const float* __restrict__ beta,
    const float* __restrict__ mean,
    const float* __restrict__ var) {
    int n = blockIdx.z;
    const float* A = g_weff + (size_t)(n * 3 + l) * (CC * CC);  // [o][b]
    const float* B = x + (size_t)n * (CC * HW);                 // [b][p]
    float* Cc = y + (size_t)n * (CC * HW);

    __shared__ float As[16][64];
    __shared__ float Bs[16][128];

    int tid = threadIdx.x;
    int row0 = blockIdx.y * 64;    // o
    int col0 = blockIdx.x * 128;   // p
    int tr = tid >> 4, tc = tid & 15;
    int arow = tid >> 2, acol4 = (tid & 3) * 4;
    int brow = tid >> 4, bcol = (tid & 15) * 8;

    u64 acc[4][4] = {};

    for (int k0 = 0; k0 < CC; k0 += 16) {
        float4 av = *(const float4*)(A + (row0 + arow) * CC + k0 + acol4);
        As[acol4 + 0][arow] = av.x;
        As[acol4 + 1][arow] = av.y;
        As[acol4 + 2][arow] = av.z;
        As[acol4 + 3][arow] = av.w;
        float4 b0 = *(const float4*)(B + (k0 + brow) * HW + col0 + bcol);
        float4 b1 = *(const float4*)(B + (k0 + brow) * HW + col0 + bcol + 4);
        *(float4*)&Bs[brow][bcol]     = b0;
        *(float4*)&Bs[brow][bcol + 4] = b1;
        __syncthreads();
#pragma unroll
        for (int k = 0; k < 16; k++) {
            float4 a4 = *(const float4*)&As[k][tr * 4];
            ulonglong2 blo = *(const ulonglong2*)&Bs[k][tc * 4];
            ulonglong2 bhi = *(const ulonglong2*)&Bs[k][64 + tc * 4];
            u64 ad[4] = {dupf(a4.x), dupf(a4.y), dupf(a4.z), dupf(a4.w)};
#pragma unroll
            for (int i = 0; i < 4; i++) {
                ffma2(acc[i][0], ad[i], blo.x);
                ffma2(acc[i][1], ad[i], blo.y);
                ffma2(acc[i][2], ad[i], bhi.x);
                ffma2(acc[i][3], ad[i], bhi.y);
            }
        }
        __syncthreads();
    }

#pragma unroll
    for (int i = 0; i < 4; i++) {
        int o = row0 + tr * 4 + i;
        float sc  = gamma[o] * rsqrtf(var[o] + 1e-5f);
        float add = (cb[o] - mean[o]) * sc + beta[o];
        float2 p0 = unpk(acc[i][0]), p1 = unpk(acc[i][1]);
        float2 p2 = unpk(acc[i][2]), p3 = unpk(acc[i][3]);
        float4 v0, v1;
        v0.x = fmaxf(fmaf(p0.x, sc, add), 0.0f);
        v0.y = fmaxf(fmaf(p0.y, sc, add), 0.0f);
        v0.z = fmaxf(fmaf(p1.x, sc, add), 0.0f);
        v0.w = fmaxf(fmaf(p1.y, sc, add), 0.0f);
        v1.x = fmaxf(fmaf(p2.x, sc, add), 0.0f);
        v1.y = fmaxf(fmaf(p2.y, sc, add), 0.0f);
        v1.z = fmaxf(fmaf(p3.x, sc, add), 0.0f);
        v1.w = fmaxf(fmaf(p3.y, sc, add), 0.0f);
        *(float4*)(Cc + o * HW + col0 + tc * 4)      = v0;
        *(float4*)(Cc + o * HW + col0 + 64 + tc * 4) = v1;
    }
}

// ---------------------------------------------------------------- launch
extern "C" void kernel_launch(void* const* d_in, const int* in_sizes, int n_in,
                              void* d_out, int out_size) {
    (void)in_sizes; (void)n_in; (void)out_size;
    const float* feats = (const float*)d_in[0];  // [4,256,32,32]
    const float* adj   = (const float*)d_in[1];  // [4,256,256]
    const float* convw = (const float*)d_in[2];  // [3,256,4096]
    const float* convb = (const float*)d_in[3];  // [3,256]
    const float* gamma = (const float*)d_in[4];
    const float* beta  = (const float*)d_in[5];
    const float* mean  = (const float*)d_in[6];
    const float* var   = (const float*)d_in[7];
    float* out = (float*)d_out;                  // [3,4,256,32,32]

    reset_kernel<<<1, 1>>>();
    detect_kernel<<<dim3(NB, SS), 256>>>(adj);
    wsum_kernel<<<768, 256>>>(convw);
    weff_kernel<<<dim3(2, 4, NB * 3), 256>>>(adj);
    corr2_kernel<<<3, 256>>>(adj, convw);

    const size_t SEC = (size_t)NB * CC * HW;
    for (int l = 0; l < 3; l++) {
        const float* x = (l == 0) ? feats : (out + (size_t)(l - 1) * SEC);
        layer_kernel<<<dim3(8, 4, NB), 256>>>(
            x, out + (size_t)l * SEC, l,
            convb + l * CC, gamma + l * CC, beta + l * CC,
            mean + l * CC, var + l * CC);
    }
}